// round 2
// baseline (speedup 1.0000x reference)
#include <cuda_runtime.h>
#include <math.h>

#define Bv 4
#define Hv 16
#define Nv 8192
#define Dv 64
#define BH (Bv*Hv)
#define SPLIT1 8
#define SPLIT2 8

// scratch (device globals: no allocation allowed)
__device__ float g_ctx[BH*Dv*Dv];    // [bh][d][e]
__device__ float g_v2sum[BH*Dv];     // [bh][d]
__device__ float g_f[BH*Nv];         // per-token denominator f

__device__ __forceinline__ float elu1(float x) {
    return x > 0.f ? x + 1.f : __expf(x);
}

__global__ void k0_zero() {
    int i = blockIdx.x*blockDim.x + threadIdx.x;
    if (i < BH*Dv*Dv) g_ctx[i] = 0.f;
    if (i < BH*Dv)    g_v2sum[i] = 0.f;
}

// Pass 1: from K,V compute v2, x, f; accumulate context = v2^T x and sum(v2).
__global__ __launch_bounds__(256) void k1_pass1(
        const float* __restrict__ Kin, const float* __restrict__ Vin,
        const float* __restrict__ mask, const float* __restrict__ curv) {
    const int bh = blockIdx.x;
    const int split = blockIdx.y;
    const float kc = curv[bh & (Hv-1)];
    const int tokens = Nv / SPLIT1;          // 1024
    const int n0 = split * tokens;
    __shared__ __align__(16) float ks[32*68];   // K tile -> v2 tile
    __shared__ __align__(16) float vs[32*68];   // V tile -> x tile
    __shared__ float smv[Dv];
    const int tid = threadIdx.x;
    if (tid < Dv) smv[tid] = 0.f;
    const float* Kb = Kin + (size_t)bh*Nv*Dv;
    const float* Vb = Vin + (size_t)bh*Nv*Dv;

    float acc[4][4];
    #pragma unroll
    for (int i=0;i<4;i++)
        #pragma unroll
        for (int j=0;j<4;j++) acc[i][j]=0.f;
    float v2loc[8];
    #pragma unroll
    for (int j=0;j<8;j++) v2loc[j]=0.f;

    const int tB = tid >> 3, sub = tid & 7;   // 32 tokens x 8 threads
    const int ty = tid >> 4, tx = tid & 15;   // 16x16 GEMM grid

    for (int c0 = 0; c0 < tokens; c0 += 32) {
        const int nb = n0 + c0;
        __syncthreads();
        // Phase A: coalesced load of 32x64 K and V tiles
        #pragma unroll
        for (int r = 0; r < 2; r++) {
            int j = tid + r*256;
            int t = j >> 4, d4 = (j & 15)*4;
            *(float4*)(ks + t*68 + d4) = *(const float4*)(Kb + (size_t)(nb+t)*Dv + d4);
            *(float4*)(vs + t*68 + d4) = *(const float4*)(Vb + (size_t)(nb+t)*Dv + d4);
        }
        __syncthreads();
        // Phase B: per-token scalars, overwrite tiles with v2 / x
        {
            const int n = nb + tB;
            float* vp = vs + tB*68 + sub*8;
            float* kp = ks + tB*68 + sub*8;
            float4 va  = *(float4*)vp;
            float4 vb4 = *(float4*)(vp+4);
            float ss = va.x*va.x + va.y*va.y + va.z*va.z + va.w*va.w
                     + vb4.x*vb4.x + vb4.y*vb4.y + vb4.z*vb4.z + vb4.w*vb4.w;
            ss += __shfl_xor_sync(0xffffffffu, ss, 1);
            ss += __shfl_xor_sync(0xffffffffu, ss, 2);
            ss += __shfl_xor_sync(0xffffffffu, ss, 4);
            float f = fmaxf(1.f + kc*ss, 1e-15f);
            float invf = 1.f / f;
            float gamma = 2.f * invf;
            float gm1 = gamma - 1.f;
            float dn = copysignf(fmaxf(fabsf(gm1), 1e-10f), gm1);  // clamp_abs
            float m = mask[n];
            float dm = dn * m;
            float gd = (gamma / dn) * m;
            float4 ka  = *(float4*)kp;
            float4 kb4 = *(float4*)(kp+4);
            float w0 = dm*elu1(ka.x*invf),  w1 = dm*elu1(ka.y*invf);
            float w2 = dm*elu1(ka.z*invf),  w3 = dm*elu1(ka.w*invf);
            float w4 = dm*elu1(kb4.x*invf), w5 = dm*elu1(kb4.y*invf);
            float w6 = dm*elu1(kb4.z*invf), w7 = dm*elu1(kb4.w*invf);
            *(float4*)kp     = make_float4(w0,w1,w2,w3);
            *(float4*)(kp+4) = make_float4(w4,w5,w6,w7);
            *(float4*)vp     = make_float4(gd*va.x,  gd*va.y,  gd*va.z,  gd*va.w);
            *(float4*)(vp+4) = make_float4(gd*vb4.x, gd*vb4.y, gd*vb4.z, gd*vb4.w);
            v2loc[0]+=w0; v2loc[1]+=w1; v2loc[2]+=w2; v2loc[3]+=w3;
            v2loc[4]+=w4; v2loc[5]+=w5; v2loc[6]+=w6; v2loc[7]+=w7;
            if (sub == 0) g_f[(size_t)bh*Nv + n] = f;
        }
        __syncthreads();
        // GEMM phase: context[d][e] += v2[t][d]*x[t][e], 4x4 per thread
        #pragma unroll 8
        for (int t = 0; t < 32; t++) {
            float4 a = *(float4*)(ks + t*68 + ty*4);
            float4 b = *(float4*)(vs + t*68 + tx*4);
            float av[4] = {a.x,a.y,a.z,a.w};
            float bw[4] = {b.x,b.y,b.z,b.w};
            #pragma unroll
            for (int i=0;i<4;i++)
                #pragma unroll
                for (int j=0;j<4;j++) acc[i][j] += av[i]*bw[j];
        }
    }
    // epilogue: merge partials
    float* ctx = g_ctx + bh*Dv*Dv;
    #pragma unroll
    for (int i=0;i<4;i++)
        #pragma unroll
        for (int j=0;j<4;j++)
            atomicAdd(&ctx[(ty*4+i)*Dv + tx*4+j], acc[i][j]);
    __syncthreads();
    #pragma unroll
    for (int j=0;j<8;j++) atomicAdd(&smv[sub*8+j], v2loc[j]);
    __syncthreads();
    if (tid < Dv) atomicAdd(&g_v2sum[bh*Dv + tid], smv[tid]);
}

// Pass 2: v1, Dn, X = (v1@context)*Dinv, fused radial geometry, write out.
__global__ __launch_bounds__(256) void k2_pass2(
        const float* __restrict__ Qin, const float* __restrict__ curv,
        float* __restrict__ Out) {
    const int bh = blockIdx.x, split = blockIdx.y;
    const float kc = curv[bh & (Hv-1)];
    const float absk = fabsf(kc);
    const float sk = sqrtf(absk + 1e-15f);
    const float maxnorm = (kc < 0.f) ? (1.f - 0.004f)/sqrtf(absk + 1e-15f) : 1e15f;
    __shared__ __align__(16) float ctx_s[Dv*68];
    __shared__ __align__(16) float qv[Dv*68];     // Q tile, then reused as v1^T tile
    __shared__ float v2s[Dv];
    __shared__ float ffs[Dv];
    __shared__ float dinv[Dv];
    const int tid = threadIdx.x;
    for (int i = tid; i < Dv*Dv; i += 256)
        ctx_s[(i>>6)*68 + (i&63)] = g_ctx[bh*Dv*Dv + i];
    if (tid < Dv) v2s[tid] = g_v2sum[bh*Dv + tid];
    const float* Qb = Qin + (size_t)bh*Nv*Dv;
    float* Ob = Out + (size_t)bh*Nv*Dv;
    const int tokens = Nv / SPLIT2;
    const int n0 = split*tokens;
    const int tB = tid >> 2, sub = tid & 3;   // 64 tokens x 4 threads
    const int ty = tid >> 4, tx = tid & 15;

    for (int c0 = 0; c0 < tokens; c0 += 64) {
        const int nb = n0 + c0;
        __syncthreads();
        // Phase A: coalesced 64x64 Q tile + f scalars
        #pragma unroll
        for (int r = 0; r < 4; r++) {
            int j = tid + r*256;
            int t = j >> 4, d4 = (j & 15)*4;
            *(float4*)(qv + t*68 + d4) = *(const float4*)(Qb + (size_t)(nb+t)*Dv + d4);
        }
        if (tid < Dv) ffs[tid] = g_f[(size_t)bh*Nv + nb + tid];
        __syncthreads();
        // Phase B: v1 into registers + Dn
        float invf = 1.f / ffs[tB];
        float v1r[16];
        float dnp = 0.f;
        #pragma unroll
        for (int r = 0; r < 4; r++) {
            int d0 = sub*16 + r*4;
            float4 q4 = *(float4*)(qv + tB*68 + d0);
            float e0 = elu1(q4.x*invf), e1 = elu1(q4.y*invf);
            float e2 = elu1(q4.z*invf), e3 = elu1(q4.w*invf);
            v1r[r*4+0]=e0; v1r[r*4+1]=e1; v1r[r*4+2]=e2; v1r[r*4+3]=e3;
            dnp += e0*v2s[d0] + e1*v2s[d0+1] + e2*v2s[d0+2] + e3*v2s[d0+3];
        }
        dnp += __shfl_xor_sync(0xffffffffu, dnp, 1);
        dnp += __shfl_xor_sync(0xffffffffu, dnp, 2);
        __syncthreads();   // all reads of qv done; now overwrite with v1^T
        #pragma unroll
        for (int r = 0; r < 16; r++) {
            int d = sub*16 + r;
            qv[d*68 + tB] = v1r[r];
        }
        if (sub == 0) dinv[tB] = 1.f / ((dnp == 0.f) ? 1e-5f : dnp);
        __syncthreads();
        // GEMM: X[t][e] = sum_d v1[t][d]*ctx[d][e], 4 tokens x 4 dims per thread
        float acc[4][4];
        #pragma unroll
        for (int i=0;i<4;i++)
            #pragma unroll
            for (int j=0;j<4;j++) acc[i][j]=0.f;
        #pragma unroll 16
        for (int d = 0; d < Dv; d++) {
            float4 a = *(float4*)(qv + d*68 + ty*4);
            float4 b = *(float4*)(ctx_s + d*68 + tx*4);
            float av[4] = {a.x,a.y,a.z,a.w};
            float bw[4] = {b.x,b.y,b.z,b.w};
            #pragma unroll
            for (int i=0;i<4;i++)
                #pragma unroll
                for (int j=0;j<4;j++) acc[i][j] += av[i]*bw[j];
        }
        // epilogue: D_inv scale + radial geometry (project, mobius 0.5, project)
        #pragma unroll
        for (int i = 0; i < 4; i++) {
            int t = ty*4 + i;
            float di = dinv[t];
            float x0 = acc[i][0]*di, x1 = acc[i][1]*di;
            float x2 = acc[i][2]*di, x3 = acc[i][3]*di;
            float ss = x0*x0 + x1*x1 + x2*x2 + x3*x3;
            ss += __shfl_xor_sync(0xffffffffu, ss, 1);
            ss += __shfl_xor_sync(0xffffffffu, ss, 2);
            ss += __shfl_xor_sync(0xffffffffu, ss, 4);
            ss += __shfl_xor_sync(0xffffffffu, ss, 8);
            float norm = fmaxf(sqrtf(ss), 1e-15f);
            float s = 1.f, n1 = norm;
            if (norm > maxnorm) { s = maxnorm/norm; n1 = maxnorm; }
            float xn = fmaxf(n1, 1e-15f);
            float tv;
            if (kc < 0.f) {
                // tanh(0.5*artanh(z))/sk == z/((1+sqrt(1-z^2))*sk)
                float z = fminf(sk*xn, 1.f - 1e-7f);
                tv = z / ((1.f + sqrtf(fmaxf(1.f - z*z, 0.f))) * sk);
            } else {
                tv = tanf(0.5f * atanf(sk*xn)) / sk;
            }
            s *= tv / xn;
            float n2 = fabsf(tv);
            if (n2 > maxnorm) s *= maxnorm/n2;
            *(float4*)(Ob + (size_t)(nb+t)*Dv + tx*4) =
                make_float4(x0*s, x1*s, x2*s, x3*s);
        }
    }
}

extern "C" void kernel_launch(void* const* d_in, const int* in_sizes, int n_in,
                              void* d_out, int out_size) {
    const float* Q    = (const float*)d_in[0];
    const float* K    = (const float*)d_in[1];
    const float* V    = (const float*)d_in[2];
    const float* mask = (const float*)d_in[3];
    const float* curv = (const float*)d_in[4];
    float* out = (float*)d_out;
    (void)in_sizes; (void)n_in; (void)out_size;

    k0_zero<<<(BH*Dv*Dv + 255)/256, 256>>>();
    k1_pass1<<<dim3(BH, SPLIT1), 256>>>(K, V, mask, curv);
    k2_pass2<<<dim3(BH, SPLIT2), 256>>>(Q, curv, out);
}